// round 11
// baseline (speedup 1.0000x reference)
#include <cuda_runtime.h>

// ---------------------------------------------------------------------------
// 3-layer GCN, symmetric norm D^{-1/2}(A+I)D^{-1/2}, self-loops.
// N=50000, E=640000, features 128 -> 128 -> 128 -> 64.
// R11: quarter-staggered agg/gemm pipeline with double-buffered H
// (gemm(k+1)[q] overlaps agg(k)[q+1..]); prep overlapped with gemm1.
// ---------------------------------------------------------------------------

#define MAX_N 50048
#define MAX_E 640000
#define SCAN_CHUNK 1024

__device__ __align__(16) float g_H[MAX_N * 128];    // H buffer A (layers 1,3)
__device__ __align__(16) float g_H2[MAX_N * 128];   // H buffer B (layer 2)
__device__ __align__(16) float g_B[MAX_N * 128];
__device__ __align__(16) float g_enorm[MAX_E];
__device__ __align__(16) int   g_src[MAX_E];
__device__ int   g_rowptr[MAX_N + 1];
__device__ int   g_cnt[MAX_N];                      // ZERO between replays
__device__ int   g_bsum[(MAX_N + SCAN_CHUNK - 1) / SCAN_CHUNK];
__device__ float g_dinv[MAX_N];
__device__ int   g_is64;

// ---------------------------------------------------------------------------
// f32x2 helpers
// ---------------------------------------------------------------------------
__device__ __forceinline__ unsigned long long dup_f32(float w) {
    unsigned long long r;
    asm("mov.b64 %0, {%1, %1};" : "=l"(r) : "f"(w));
    return r;
}
__device__ __forceinline__ void ffma2(unsigned long long& d,
                                      unsigned long long a,
                                      unsigned long long b) {
    asm("fma.rn.f32x2 %0, %1, %2, %0;" : "+l"(d) : "l"(a), "l"(b));
}
__device__ __forceinline__ void unpack2(unsigned long long v, float& lo, float& hi) {
    asm("mov.b64 {%0, %1}, %2;" : "=f"(lo), "=f"(hi) : "l"(v));
}

// ---------------------------------------------------------------------------
// Prep
// ---------------------------------------------------------------------------
__global__ void detect_dtype_kernel(const void* __restrict__ ei, int E, int N) {
    int tid = threadIdx.x;
    const long long* p = (const long long*)ei;
    int take = E < 128 ? E : 128;
    int bad = 0;
    for (int j = tid * 4; j < tid * 4 + 4; j++) {
        if (j < take) {
            long long v = p[j];
            if (v < 0 || v >= (long long)N) bad = 1;
        }
    }
    unsigned m = __ballot_sync(0xffffffffu, bad);
    if (tid == 0) g_is64 = (m == 0u);
}

__device__ __forceinline__ void decode_edge(const void* ei, int E, int e,
                                            int& s, int& d) {
    if (g_is64) {
        const long long* p = (const long long*)ei;
        s = (int)p[e];
        d = (int)p[E + e];
    } else {
        const int* p = (const int*)ei;
        s = p[e];
        d = p[E + e];
    }
}

__global__ void count_kernel(const void* __restrict__ ei, int E) {
    int e = blockIdx.x * blockDim.x + threadIdx.x;
    if (e >= E) return;
    int d;
    if (g_is64) d = (int)((const long long*)ei)[E + e];
    else        d = ((const int*)ei)[E + e];
    atomicAdd(&g_cnt[d], 1);
}

__global__ void scan1_kernel(int n) {
    __shared__ int warpsum[8];
    const int tid = threadIdx.x, lane = tid & 31, wid = tid >> 5;
    const int base = blockIdx.x * SCAN_CHUNK + tid * 4;

    int v[4] = {0, 0, 0, 0};
    if (base + 3 < n) {
        *reinterpret_cast<int4*>(v) = *reinterpret_cast<const int4*>(&g_cnt[base]);
    } else {
        for (int j = 0; j < 4; j++) if (base + j < n) v[j] = g_cnt[base + j];
    }
    #pragma unroll
    for (int j = 0; j < 4; j++)
        if (base + j < n) g_dinv[base + j] = rsqrtf((float)v[j] + 1.0f);

    int t0 = v[0], t1 = t0 + v[1], t2 = t1 + v[2], t3 = t2 + v[3];
    int x = t3;
    #pragma unroll
    for (int off = 1; off < 32; off <<= 1) {
        int t = __shfl_up_sync(0xffffffffu, x, off);
        if (lane >= off) x += t;
    }
    if (lane == 31) warpsum[wid] = x;
    __syncthreads();
    if (wid == 0 && lane < 8) {
        int w = warpsum[lane];
        #pragma unroll
        for (int off = 1; off < 8; off <<= 1) {
            int t = __shfl_up_sync(0xffu, w, off);
            if (lane >= off) w += t;
        }
        warpsum[lane] = w;
    }
    __syncthreads();

    int off = (x - t3) + (wid > 0 ? warpsum[wid - 1] : 0);
    int pre[4] = {0, t0, t1, t2};
    #pragma unroll
    for (int j = 0; j < 4; j++)
        if (base + j < n) g_rowptr[base + j] = off + pre[j];

    if (tid == 255) g_bsum[blockIdx.x] = warpsum[7];
}

__global__ void scan2_kernel(int nb, int n) {
    __shared__ int ws[2];
    int tid = threadIdx.x, lane = tid & 31, wid = tid >> 5;
    int v = (tid < nb) ? g_bsum[tid] : 0;
    int x = v;
    #pragma unroll
    for (int off = 1; off < 32; off <<= 1) {
        int t = __shfl_up_sync(0xffffffffu, x, off);
        if (lane >= off) x += t;
    }
    if (lane == 31) ws[wid] = x;
    __syncthreads();
    if (wid == 1) x += ws[0];
    if (tid < nb) g_bsum[tid] = x - v;
    if (tid == nb - 1) g_rowptr[n] = x;
}

__global__ void scan3_kernel(int n) {
    int i = blockIdx.x * blockDim.x + threadIdx.x;
    if (i < n) g_rowptr[i] += g_bsum[i >> 10];
}

__global__ void fill_kernel(const void* __restrict__ ei, int E) {
    int e = blockIdx.x * blockDim.x + threadIdx.x;
    if (e >= E) return;
    int s, d;
    decode_edge(ei, E, e, s, d);
    int pos = g_rowptr[d] + atomicSub(&g_cnt[d], 1) - 1;
    g_src[pos] = s;
    g_enorm[pos] = g_dinv[s] * g_dinv[d];
}

// ---------------------------------------------------------------------------
// FFMA2 register-tiled SGEMM over rows [rowBegin, rowEnd): H<out> = X @ W
// TO_H2 selects output buffer (double buffering across layers).
// ---------------------------------------------------------------------------
template <int BN, bool RELU, bool FROM_GB, bool TO_H2>
__global__ __launch_bounds__(256, 2)
void gemm_kernel(const float* __restrict__ Xin,
                 const float* __restrict__ W, int rowBegin, int rowEnd) {
    constexpr int BM = 128, BK = 16;
    constexpr int TN = BN / 16;
    constexpr int WI = (BK * BN) / 1024;

    __shared__ float Xs[BK][BM + 4];
    __shared__ float Ws[BK][BN];

    const float* __restrict__ X = FROM_GB ? (const float*)g_B : Xin;
    float* __restrict__ Hout = TO_H2 ? g_H2 : g_H;

    const int tid = threadIdx.x;
    const int tx = tid & 15;
    const int ty = tid >> 4;
    const int rowBase = rowBegin + blockIdx.x * BM;

    const int xrow0 = tid >> 2, xkq0 = tid & 3;
    const int xrow1 = (tid + 256) >> 2, xkq1 = (tid + 256) & 3;
    const int r0 = rowBase + xrow0, r1 = rowBase + xrow1;

    float4 xr[2], wr[2];

    auto load_tile = [&](int kc) {
        xr[0] = make_float4(0.f, 0.f, 0.f, 0.f);
        xr[1] = make_float4(0.f, 0.f, 0.f, 0.f);
        if (r0 < rowEnd)
            xr[0] = *reinterpret_cast<const float4*>(&X[(size_t)r0 * 128 + kc + xkq0 * 4]);
        if (r1 < rowEnd)
            xr[1] = *reinterpret_cast<const float4*>(&X[(size_t)r1 * 128 + kc + xkq1 * 4]);
        if (RELU) {
            xr[0].x = fmaxf(xr[0].x, 0.f); xr[0].y = fmaxf(xr[0].y, 0.f);
            xr[0].z = fmaxf(xr[0].z, 0.f); xr[0].w = fmaxf(xr[0].w, 0.f);
            xr[1].x = fmaxf(xr[1].x, 0.f); xr[1].y = fmaxf(xr[1].y, 0.f);
            xr[1].z = fmaxf(xr[1].z, 0.f); xr[1].w = fmaxf(xr[1].w, 0.f);
        }
        #pragma unroll
        for (int i = 0; i < WI; i++) {
            int j = tid + 256 * i;
            int kk = j / (BN / 4);
            int cc = j % (BN / 4);
            wr[i] = *reinterpret_cast<const float4*>(&W[(size_t)(kc + kk) * BN + cc * 4]);
        }
    };
    auto store_tile = [&]() {
        Xs[xkq0 * 4 + 0][xrow0] = xr[0].x;
        Xs[xkq0 * 4 + 1][xrow0] = xr[0].y;
        Xs[xkq0 * 4 + 2][xrow0] = xr[0].z;
        Xs[xkq0 * 4 + 3][xrow0] = xr[0].w;
        Xs[xkq1 * 4 + 0][xrow1] = xr[1].x;
        Xs[xkq1 * 4 + 1][xrow1] = xr[1].y;
        Xs[xkq1 * 4 + 2][xrow1] = xr[1].z;
        Xs[xkq1 * 4 + 3][xrow1] = xr[1].w;
        #pragma unroll
        for (int i = 0; i < WI; i++) {
            int j = tid + 256 * i;
            int kk = j / (BN / 4);
            int cc = j % (BN / 4);
            *reinterpret_cast<float4*>(&Ws[kk][cc * 4]) = wr[i];
        }
    };

    unsigned long long acc2[4][TN];
    #pragma unroll
    for (int i = 0; i < 4; i++)
        #pragma unroll
        for (int j = 0; j < TN; j++) acc2[i][j] = 0ull;

    load_tile(0);
    store_tile();
    __syncthreads();

    for (int t = 0; t < 128 / BK; t++) {
        if (t + 1 < 128 / BK) load_tile((t + 1) * BK);

        #pragma unroll
        for (int k = 0; k < BK; k++) {
            const ulonglong2* ap =
                reinterpret_cast<const ulonglong2*>(&Xs[k][ty * 8]);
            ulonglong2 a01 = ap[0];
            ulonglong2 a23 = ap[1];
            unsigned long long a2[4] = {a01.x, a01.y, a23.x, a23.y};

            float bw[TN];
            #pragma unroll
            for (int j = 0; j < TN; j += 4)
                *reinterpret_cast<float4*>(&bw[j]) =
                    *reinterpret_cast<const float4*>(&Ws[k][tx * TN + j]);
            unsigned long long b2[TN];
            #pragma unroll
            for (int j = 0; j < TN; j++) b2[j] = dup_f32(bw[j]);

            #pragma unroll
            for (int rp = 0; rp < 4; rp++)
                #pragma unroll
                for (int j = 0; j < TN; j++)
                    ffma2(acc2[rp][j], a2[rp], b2[j]);
        }
        __syncthreads();
        if (t + 1 < 128 / BK) {
            store_tile();
            __syncthreads();
        }
    }

    #pragma unroll
    for (int rp = 0; rp < 4; rp++) {
        float h0[TN], h1[TN];
        #pragma unroll
        for (int j = 0; j < TN; j++) unpack2(acc2[rp][j], h0[j], h1[j]);
        int row0 = rowBase + ty * 8 + 2 * rp;
        #pragma unroll
        for (int half = 0; half < 2; half++) {
            int row = row0 + half;
            if (row >= rowEnd) continue;
            float* h = half ? h1 : h0;
            size_t base = (size_t)row * BN + tx * TN;
            #pragma unroll
            for (int j = 0; j < TN; j += 4)
                *reinterpret_cast<float4*>(&Hout[base + j]) =
                    *reinterpret_cast<const float4*>(&h[j]);
        }
    }
}

// ---------------------------------------------------------------------------
// F=128 aggregation over [begin, end): warp per node. FROM_H2 selects source.
// ---------------------------------------------------------------------------
template <bool FROM_H2>
__global__ void aggregate128_kernel(const float* __restrict__ bias,
                                    int begin, int end) {
    int node = begin + ((blockIdx.x * blockDim.x + threadIdx.x) >> 5);
    int lane = threadIdx.x & 31;
    if (node >= end) return;

    int e = g_rowptr[node];
    const int eend = g_rowptr[node + 1];

    const float4* __restrict__ H4 =
        reinterpret_cast<const float4*>(FROM_H2 ? g_H2 : g_H);
    float di = g_dinv[node];
    float s = di * di;
    float4 hd = H4[(size_t)node * 32 + lane];
    float4 bb = reinterpret_cast<const float4*>(bias)[lane];
    float4 acc = make_float4(fmaf(hd.x, s, bb.x), fmaf(hd.y, s, bb.y),
                             fmaf(hd.z, s, bb.z), fmaf(hd.w, s, bb.w));

    for (; e + 7 < eend; e += 8) {
        int   si[8];
        float ni[8];
        #pragma unroll
        for (int j = 0; j < 8; j++) { si[j] = __ldg(&g_src[e + j]); ni[j] = __ldg(&g_enorm[e + j]); }
        float4 v[8];
        #pragma unroll
        for (int j = 0; j < 8; j++) v[j] = H4[(size_t)si[j] * 32 + lane];
        #pragma unroll
        for (int j = 0; j < 8; j++) {
            acc.x = fmaf(v[j].x, ni[j], acc.x);
            acc.y = fmaf(v[j].y, ni[j], acc.y);
            acc.z = fmaf(v[j].z, ni[j], acc.z);
            acc.w = fmaf(v[j].w, ni[j], acc.w);
        }
    }
    for (; e < eend; e++) {
        int s0 = __ldg(&g_src[e]);
        float n0 = __ldg(&g_enorm[e]);
        float4 v0 = H4[(size_t)s0 * 32 + lane];
        acc.x = fmaf(v0.x, n0, acc.x);
        acc.y = fmaf(v0.y, n0, acc.y);
        acc.z = fmaf(v0.z, n0, acc.z);
        acc.w = fmaf(v0.w, n0, acc.w);
    }

    reinterpret_cast<float4*>(g_B)[(size_t)node * 32 + lane] = acc;
}

// ---------------------------------------------------------------------------
// F=64 aggregation over [begin, end): two nodes per warp, reads g_H (H1),
// writes d_out.
// ---------------------------------------------------------------------------
__global__ void aggregate64_kernel(const float* __restrict__ bias,
                                   float* __restrict__ outp,
                                   int begin, int end) {
    int warp = (blockIdx.x * blockDim.x + threadIdx.x) >> 5;
    int lane = threadIdx.x & 31;
    int node = begin + warp * 2 + (lane >> 4);
    int l16 = lane & 15;
    if (node >= end) return;

    int e = g_rowptr[node];
    const int eend = g_rowptr[node + 1];

    const float4* __restrict__ H4 = reinterpret_cast<const float4*>(g_H);
    float di = g_dinv[node];
    float s = di * di;
    float4 hd = H4[(size_t)node * 16 + l16];
    float4 bb = reinterpret_cast<const float4*>(bias)[l16];
    float4 acc = make_float4(fmaf(hd.x, s, bb.x), fmaf(hd.y, s, bb.y),
                             fmaf(hd.z, s, bb.z), fmaf(hd.w, s, bb.w));

    for (; e + 3 < eend; e += 4) {
        int s0 = __ldg(&g_src[e]), s1 = __ldg(&g_src[e + 1]);
        int s2 = __ldg(&g_src[e + 2]), s3 = __ldg(&g_src[e + 3]);
        float n0 = __ldg(&g_enorm[e]), n1 = __ldg(&g_enorm[e + 1]);
        float n2 = __ldg(&g_enorm[e + 2]), n3 = __ldg(&g_enorm[e + 3]);
        float4 v0 = H4[(size_t)s0 * 16 + l16];
        float4 v1 = H4[(size_t)s1 * 16 + l16];
        float4 v2 = H4[(size_t)s2 * 16 + l16];
        float4 v3 = H4[(size_t)s3 * 16 + l16];
        acc.x += v0.x * n0 + v1.x * n1 + v2.x * n2 + v3.x * n3;
        acc.y += v0.y * n0 + v1.y * n1 + v2.y * n2 + v3.y * n3;
        acc.z += v0.z * n0 + v1.z * n1 + v2.z * n2 + v3.z * n3;
        acc.w += v0.w * n0 + v1.w * n1 + v2.w * n2 + v3.w * n3;
    }
    for (; e < eend; e++) {
        int s0 = __ldg(&g_src[e]);
        float n0 = __ldg(&g_enorm[e]);
        float4 v0 = H4[(size_t)s0 * 16 + l16];
        acc.x = fmaf(v0.x, n0, acc.x);
        acc.y = fmaf(v0.y, n0, acc.y);
        acc.z = fmaf(v0.z, n0, acc.z);
        acc.w = fmaf(v0.w, n0, acc.w);
    }

    reinterpret_cast<float4*>(outp)[(size_t)node * 16 + l16] = acc;
}

// ---------------------------------------------------------------------------
// Launch: quarter-staggered pipeline.
//   s2: prep -> agg1 quarters -> agg2 quarters -> agg64 half1
//   s0: gemm1 -> gemm2 quarters (gated per agg1 quarter) -> gemm3 quarters
//       (gated per agg2 quarter) -> agg64 half0
// ---------------------------------------------------------------------------
extern "C" void kernel_launch(void* const* d_in, const int* in_sizes, int n_in,
                              void* d_out, int out_size) {
    const float* x  = (const float*)d_in[0];
    const void*  ei = d_in[1];
    const float* W1 = (const float*)d_in[2];
    const float* b1 = (const float*)d_in[3];
    const float* W2 = (const float*)d_in[4];
    const float* b2 = (const float*)d_in[5];
    const float* W3 = (const float*)d_in[6];
    const float* b3 = (const float*)d_in[7];
    float* out = (float*)d_out;

    const int N = in_sizes[0] / 128;
    const int E = in_sizes[1] / 2;
    const int T = 256;
    const int nb = (N + SCAN_CHUNK - 1) / SCAN_CHUNK;

    // quarter boundaries, 128-aligned
    int QA = ((N + 511) / 512 + 0) * 128;      // ceil(N/4) rounded up to 128
    int qb[5];
    qb[0] = 0;
    for (int i = 1; i < 4; i++) qb[i] = (QA * i < N) ? QA * i : N;
    qb[4] = N;

    static cudaStream_t s2 = nullptr;
    static cudaEvent_t ev[16];
    if (!s2) {
        cudaStreamCreateWithFlags(&s2, cudaStreamNonBlocking);
        for (int i = 0; i < 16; i++)
            cudaEventCreateWithFlags(&ev[i], cudaEventDisableTiming);
    }
    // ev[0]=fork  ev[1]=H1 done  ev[2..5]=agg1 quarters  ev[6]=gemm2 done
    // ev[7..10]=agg2 quarters  ev[11]=gemm3 done  ev[12]=agg64 h1 done

    const int Nh = (N + 1) / 2;

    // ---- fork: prep on s2, gemm1 on s0 ----
    cudaEventRecord(ev[0], 0);
    cudaStreamWaitEvent(s2, ev[0], 0);

    detect_dtype_kernel<<<1, 32, 0, s2>>>(ei, E, N);
    count_kernel<<<(E + T - 1) / T, T, 0, s2>>>(ei, E);
    scan1_kernel<<<nb, 256, 0, s2>>>(N);
    scan2_kernel<<<1, 64, 0, s2>>>(nb, N);
    scan3_kernel<<<(N + T - 1) / T, T, 0, s2>>>(N);
    fill_kernel<<<(E + T - 1) / T, T, 0, s2>>>(ei, E);

    gemm_kernel<128, false, false, false><<<(N + 127) / 128, 256>>>(x, W1, 0, N);
    cudaEventRecord(ev[1], 0);  // H1 complete

    // ---- boundary 1: agg1 quarters (s2) / gemm2 quarters (s0) ----
    cudaStreamWaitEvent(s2, ev[1], 0);
    for (int q = 0; q < 4; q++) {
        int b = qb[q], e = qb[q + 1];
        if (b >= e) { cudaEventRecord(ev[2 + q], s2); continue; }
        aggregate128_kernel<false><<<((e - b) * 32 + T - 1) / T, T, 0, s2>>>(b1, b, e);
        cudaEventRecord(ev[2 + q], s2);
    }
    for (int q = 0; q < 4; q++) {
        int b = qb[q], e = qb[q + 1];
        cudaStreamWaitEvent(0, ev[2 + q], 0);
        if (b >= e) continue;
        gemm_kernel<128, true, true, true><<<(e - b + 127) / 128, 256>>>(nullptr, W2, b, e);
    }
    cudaEventRecord(ev[6], 0);  // H2 complete

    // ---- boundary 2: agg2 quarters (s2) / gemm3 quarters (s0) ----
    cudaStreamWaitEvent(s2, ev[6], 0);
    for (int q = 0; q < 4; q++) {
        int b = qb[q], e = qb[q + 1];
        if (b >= e) { cudaEventRecord(ev[7 + q], s2); continue; }
        aggregate128_kernel<true><<<((e - b) * 32 + T - 1) / T, T, 0, s2>>>(b2, b, e);
        cudaEventRecord(ev[7 + q], s2);
    }
    for (int q = 0; q < 4; q++) {
        int b = qb[q], e = qb[q + 1];
        cudaStreamWaitEvent(0, ev[7 + q], 0);
        if (b >= e) continue;
        gemm_kernel<64, true, true, false><<<(e - b + 127) / 128, 256>>>(nullptr, W3, b, e);
    }
    cudaEventRecord(ev[11], 0);  // H3 complete

    // ---- final aggregation halves on both streams ----
    aggregate64_kernel<<<(((Nh + 1) / 2) * 32 + T - 1) / T, T>>>(b3, out, 0, Nh);

    cudaStreamWaitEvent(s2, ev[11], 0);
    aggregate64_kernel<<<(((N - Nh + 1) / 2) * 32 + T - 1) / T, T, 0, s2>>>(
        b3, out, Nh, N);
    cudaEventRecord(ev[12], s2);

    cudaStreamWaitEvent(0, ev[12], 0);
}

// round 13
// speedup vs baseline: 1.2584x; 1.2584x over previous
#include <cuda_runtime.h>
#include <cstdint>

// ---------------------------------------------------------------------------
// 3-layer GCN, symmetric norm D^{-1/2}(A+I)D^{-1/2}, self-loops.
// N=50000, E=640000, features 128 -> 128 -> 128 -> 64.
// R13: R10 schedule (two-stream halves, prep || gemm1) + packed (src,norm)
// uint2 edge records (single 8B scatter in fill, single 8B load in agg).
// NOTE: tcgen05 unusable — harness PTX target is compute_103 (no 'a').
// ---------------------------------------------------------------------------

#define MAX_N 50048
#define MAX_E 640000
#define SCAN_CHUNK 1024

__device__ __align__(16) float g_H[MAX_N * 128];
__device__ __align__(16) float g_B[MAX_N * 128];
__device__ __align__(16) uint2 g_edge8[MAX_E];      // {src, __float_as_uint(norm)}
__device__ int   g_rowptr[MAX_N + 1];
__device__ int   g_cnt[MAX_N];                      // ZERO between replays
__device__ int   g_bsum[(MAX_N + SCAN_CHUNK - 1) / SCAN_CHUNK];
__device__ float g_dinv[MAX_N];
__device__ int   g_is64;

// ---------------------------------------------------------------------------
// f32x2 helpers
// ---------------------------------------------------------------------------
__device__ __forceinline__ unsigned long long dup_f32(float w) {
    unsigned long long r;
    asm("mov.b64 %0, {%1, %1};" : "=l"(r) : "f"(w));
    return r;
}
__device__ __forceinline__ void ffma2(unsigned long long& d,
                                      unsigned long long a,
                                      unsigned long long b) {
    asm("fma.rn.f32x2 %0, %1, %2, %0;" : "+l"(d) : "l"(a), "l"(b));
}
__device__ __forceinline__ void unpack2(unsigned long long v, float& lo, float& hi) {
    asm("mov.b64 {%0, %1}, %2;" : "=f"(lo), "=f"(hi) : "l"(v));
}

// ---------------------------------------------------------------------------
// Prep
// ---------------------------------------------------------------------------
__global__ void detect_dtype_kernel(const void* __restrict__ ei, int E, int N) {
    int tid = threadIdx.x;
    const long long* p = (const long long*)ei;
    int take = E < 128 ? E : 128;
    int bad = 0;
    for (int j = tid * 4; j < tid * 4 + 4; j++) {
        if (j < take) {
            long long v = p[j];
            if (v < 0 || v >= (long long)N) bad = 1;
        }
    }
    unsigned m = __ballot_sync(0xffffffffu, bad);
    if (tid == 0) g_is64 = (m == 0u);
}

__device__ __forceinline__ void decode_edge(const void* ei, int E, int e,
                                            int& s, int& d) {
    if (g_is64) {
        const long long* p = (const long long*)ei;
        s = (int)p[e];
        d = (int)p[E + e];
    } else {
        const int* p = (const int*)ei;
        s = p[e];
        d = p[E + e];
    }
}

__global__ void count_kernel(const void* __restrict__ ei, int E) {
    int e = blockIdx.x * blockDim.x + threadIdx.x;
    if (e >= E) return;
    int d;
    if (g_is64) d = (int)((const long long*)ei)[E + e];
    else        d = ((const int*)ei)[E + e];
    atomicAdd(&g_cnt[d], 1);
}

__global__ void scan1_kernel(int n) {
    __shared__ int warpsum[8];
    const int tid = threadIdx.x, lane = tid & 31, wid = tid >> 5;
    const int base = blockIdx.x * SCAN_CHUNK + tid * 4;

    int v[4] = {0, 0, 0, 0};
    if (base + 3 < n) {
        *reinterpret_cast<int4*>(v) = *reinterpret_cast<const int4*>(&g_cnt[base]);
    } else {
        for (int j = 0; j < 4; j++) if (base + j < n) v[j] = g_cnt[base + j];
    }
    #pragma unroll
    for (int j = 0; j < 4; j++)
        if (base + j < n) g_dinv[base + j] = rsqrtf((float)v[j] + 1.0f);

    int t0 = v[0], t1 = t0 + v[1], t2 = t1 + v[2], t3 = t2 + v[3];
    int x = t3;
    #pragma unroll
    for (int off = 1; off < 32; off <<= 1) {
        int t = __shfl_up_sync(0xffffffffu, x, off);
        if (lane >= off) x += t;
    }
    if (lane == 31) warpsum[wid] = x;
    __syncthreads();
    if (wid == 0 && lane < 8) {
        int w = warpsum[lane];
        #pragma unroll
        for (int off = 1; off < 8; off <<= 1) {
            int t = __shfl_up_sync(0xffu, w, off);
            if (lane >= off) w += t;
        }
        warpsum[lane] = w;
    }
    __syncthreads();

    int off = (x - t3) + (wid > 0 ? warpsum[wid - 1] : 0);
    int pre[4] = {0, t0, t1, t2};
    #pragma unroll
    for (int j = 0; j < 4; j++)
        if (base + j < n) g_rowptr[base + j] = off + pre[j];

    if (tid == 255) g_bsum[blockIdx.x] = warpsum[7];
}

__global__ void scan2_kernel(int nb, int n) {
    __shared__ int ws[2];
    int tid = threadIdx.x, lane = tid & 31, wid = tid >> 5;
    int v = (tid < nb) ? g_bsum[tid] : 0;
    int x = v;
    #pragma unroll
    for (int off = 1; off < 32; off <<= 1) {
        int t = __shfl_up_sync(0xffffffffu, x, off);
        if (lane >= off) x += t;
    }
    if (lane == 31) ws[wid] = x;
    __syncthreads();
    if (wid == 1) x += ws[0];
    if (tid < nb) g_bsum[tid] = x - v;
    if (tid == nb - 1) g_rowptr[n] = x;
}

__global__ void scan3_kernel(int n) {
    int i = blockIdx.x * blockDim.x + threadIdx.x;
    if (i < n) g_rowptr[i] += g_bsum[i >> 10];
}

// Fill sorted packed edges. atomicSub restores g_cnt to 0 (invariant).
__global__ void fill_kernel(const void* __restrict__ ei, int E) {
    int e = blockIdx.x * blockDim.x + threadIdx.x;
    if (e >= E) return;
    int s, d;
    decode_edge(ei, E, e, s, d);
    int pos = g_rowptr[d] + atomicSub(&g_cnt[d], 1) - 1;
    g_edge8[pos] = make_uint2((unsigned)s,
                              __float_as_uint(g_dinv[s] * g_dinv[d]));
}

// ---------------------------------------------------------------------------
// FFMA2 register-tiled SGEMM over rows [rowBegin, rowEnd): g_H = X @ W
// ---------------------------------------------------------------------------
template <int BN, bool RELU, bool FROM_GB>
__global__ __launch_bounds__(256, 2)
void gemm_kernel(const float* __restrict__ Xin,
                 const float* __restrict__ W, int rowBegin, int rowEnd) {
    constexpr int BM = 128, BK = 16;
    constexpr int TN = BN / 16;
    constexpr int WI = (BK * BN) / 1024;

    __shared__ float Xs[BK][BM + 4];
    __shared__ float Ws[BK][BN];

    const float* __restrict__ X = FROM_GB ? (const float*)g_B : Xin;

    const int tid = threadIdx.x;
    const int tx = tid & 15;
    const int ty = tid >> 4;
    const int rowBase = rowBegin + blockIdx.x * BM;

    const int xrow0 = tid >> 2, xkq0 = tid & 3;
    const int xrow1 = (tid + 256) >> 2, xkq1 = (tid + 256) & 3;
    const int r0 = rowBase + xrow0, r1 = rowBase + xrow1;

    float4 xr[2], wr[2];

    auto load_tile = [&](int kc) {
        xr[0] = make_float4(0.f, 0.f, 0.f, 0.f);
        xr[1] = make_float4(0.f, 0.f, 0.f, 0.f);
        if (r0 < rowEnd)
            xr[0] = *reinterpret_cast<const float4*>(&X[(size_t)r0 * 128 + kc + xkq0 * 4]);
        if (r1 < rowEnd)
            xr[1] = *reinterpret_cast<const float4*>(&X[(size_t)r1 * 128 + kc + xkq1 * 4]);
        if (RELU) {
            xr[0].x = fmaxf(xr[0].x, 0.f); xr[0].y = fmaxf(xr[0].y, 0.f);
            xr[0].z = fmaxf(xr[0].z, 0.f); xr[0].w = fmaxf(xr[0].w, 0.f);
            xr[1].x = fmaxf(xr[1].x, 0.f); xr[1].y = fmaxf(xr[1].y, 0.f);
            xr[1].z = fmaxf(xr[1].z, 0.f); xr[1].w = fmaxf(xr[1].w, 0.f);
        }
        #pragma unroll
        for (int i = 0; i < WI; i++) {
            int j = tid + 256 * i;
            int kk = j / (BN / 4);
            int cc = j % (BN / 4);
            wr[i] = *reinterpret_cast<const float4*>(&W[(size_t)(kc + kk) * BN + cc * 4]);
        }
    };
    auto store_tile = [&]() {
        Xs[xkq0 * 4 + 0][xrow0] = xr[0].x;
        Xs[xkq0 * 4 + 1][xrow0] = xr[0].y;
        Xs[xkq0 * 4 + 2][xrow0] = xr[0].z;
        Xs[xkq0 * 4 + 3][xrow0] = xr[0].w;
        Xs[xkq1 * 4 + 0][xrow1] = xr[1].x;
        Xs[xkq1 * 4 + 1][xrow1] = xr[1].y;
        Xs[xkq1 * 4 + 2][xrow1] = xr[1].z;
        Xs[xkq1 * 4 + 3][xrow1] = xr[1].w;
        #pragma unroll
        for (int i = 0; i < WI; i++) {
            int j = tid + 256 * i;
            int kk = j / (BN / 4);
            int cc = j % (BN / 4);
            *reinterpret_cast<float4*>(&Ws[kk][cc * 4]) = wr[i];
        }
    };

    unsigned long long acc2[4][TN];
    #pragma unroll
    for (int i = 0; i < 4; i++)
        #pragma unroll
        for (int j = 0; j < TN; j++) acc2[i][j] = 0ull;

    load_tile(0);
    store_tile();
    __syncthreads();

    for (int t = 0; t < 128 / BK; t++) {
        if (t + 1 < 128 / BK) load_tile((t + 1) * BK);

        #pragma unroll
        for (int k = 0; k < BK; k++) {
            const ulonglong2* ap =
                reinterpret_cast<const ulonglong2*>(&Xs[k][ty * 8]);
            ulonglong2 a01 = ap[0];
            ulonglong2 a23 = ap[1];
            unsigned long long a2[4] = {a01.x, a01.y, a23.x, a23.y};

            float bw[TN];
            #pragma unroll
            for (int j = 0; j < TN; j += 4)
                *reinterpret_cast<float4*>(&bw[j]) =
                    *reinterpret_cast<const float4*>(&Ws[k][tx * TN + j]);
            unsigned long long b2[TN];
            #pragma unroll
            for (int j = 0; j < TN; j++) b2[j] = dup_f32(bw[j]);

            #pragma unroll
            for (int rp = 0; rp < 4; rp++)
                #pragma unroll
                for (int j = 0; j < TN; j++)
                    ffma2(acc2[rp][j], a2[rp], b2[j]);
        }
        __syncthreads();
        if (t + 1 < 128 / BK) {
            store_tile();
            __syncthreads();
        }
    }

    #pragma unroll
    for (int rp = 0; rp < 4; rp++) {
        float h0[TN], h1[TN];
        #pragma unroll
        for (int j = 0; j < TN; j++) unpack2(acc2[rp][j], h0[j], h1[j]);
        int row0 = rowBase + ty * 8 + 2 * rp;
        #pragma unroll
        for (int half = 0; half < 2; half++) {
            int row = row0 + half;
            if (row >= rowEnd) continue;
            float* h = half ? h1 : h0;
            size_t base = (size_t)row * BN + tx * TN;
            #pragma unroll
            for (int j = 0; j < TN; j += 4)
                *reinterpret_cast<float4*>(&g_H[base + j]) =
                    *reinterpret_cast<const float4*>(&h[j]);
        }
    }
}

// ---------------------------------------------------------------------------
// F=128 aggregation over [begin, end): warp per node, packed edge loads.
// ---------------------------------------------------------------------------
__global__ void aggregate128_kernel(const float* __restrict__ bias,
                                    int begin, int end) {
    int node = begin + ((blockIdx.x * blockDim.x + threadIdx.x) >> 5);
    int lane = threadIdx.x & 31;
    if (node >= end) return;

    int e = g_rowptr[node];
    const int eend = g_rowptr[node + 1];

    const float4* __restrict__ H4 = reinterpret_cast<const float4*>(g_H);
    float di = g_dinv[node];
    float s = di * di;
    float4 hd = H4[(size_t)node * 32 + lane];
    float4 bb = reinterpret_cast<const float4*>(bias)[lane];
    float4 acc = make_float4(fmaf(hd.x, s, bb.x), fmaf(hd.y, s, bb.y),
                             fmaf(hd.z, s, bb.z), fmaf(hd.w, s, bb.w));

    for (; e + 7 < eend; e += 8) {
        uint2 ed[8];
        #pragma unroll
        for (int j = 0; j < 8; j++) ed[j] = __ldg(&g_edge8[e + j]);
        float4 v[8];
        #pragma unroll
        for (int j = 0; j < 8; j++)
            v[j] = H4[(size_t)ed[j].x * 32 + lane];
        #pragma unroll
        for (int j = 0; j < 8; j++) {
            float nj = __uint_as_float(ed[j].y);
            acc.x = fmaf(v[j].x, nj, acc.x);
            acc.y = fmaf(v[j].y, nj, acc.y);
            acc.z = fmaf(v[j].z, nj, acc.z);
            acc.w = fmaf(v[j].w, nj, acc.w);
        }
    }
    for (; e < eend; e++) {
        uint2 ed = __ldg(&g_edge8[e]);
        float nj = __uint_as_float(ed.y);
        float4 v0 = H4[(size_t)ed.x * 32 + lane];
        acc.x = fmaf(v0.x, nj, acc.x);
        acc.y = fmaf(v0.y, nj, acc.y);
        acc.z = fmaf(v0.z, nj, acc.z);
        acc.w = fmaf(v0.w, nj, acc.w);
    }

    reinterpret_cast<float4*>(g_B)[(size_t)node * 32 + lane] = acc;
}

// ---------------------------------------------------------------------------
// F=64 aggregation over [begin, end): two nodes per warp, writes d_out.
// ---------------------------------------------------------------------------
__global__ void aggregate64_kernel(const float* __restrict__ bias,
                                   float* __restrict__ outp,
                                   int begin, int end) {
    int warp = (blockIdx.x * blockDim.x + threadIdx.x) >> 5;
    int lane = threadIdx.x & 31;
    int node = begin + warp * 2 + (lane >> 4);
    int l16 = lane & 15;
    if (node >= end) return;

    int e = g_rowptr[node];
    const int eend = g_rowptr[node + 1];

    const float4* __restrict__ H4 = reinterpret_cast<const float4*>(g_H);
    float di = g_dinv[node];
    float s = di * di;
    float4 hd = H4[(size_t)node * 16 + l16];
    float4 bb = reinterpret_cast<const float4*>(bias)[l16];
    float4 acc = make_float4(fmaf(hd.x, s, bb.x), fmaf(hd.y, s, bb.y),
                             fmaf(hd.z, s, bb.z), fmaf(hd.w, s, bb.w));

    for (; e + 3 < eend; e += 4) {
        uint2 ed[4];
        #pragma unroll
        for (int j = 0; j < 4; j++) ed[j] = __ldg(&g_edge8[e + j]);
        float4 v[4];
        #pragma unroll
        for (int j = 0; j < 4; j++)
            v[j] = H4[(size_t)ed[j].x * 16 + l16];
        #pragma unroll
        for (int j = 0; j < 4; j++) {
            float nj = __uint_as_float(ed[j].y);
            acc.x = fmaf(v[j].x, nj, acc.x);
            acc.y = fmaf(v[j].y, nj, acc.y);
            acc.z = fmaf(v[j].z, nj, acc.z);
            acc.w = fmaf(v[j].w, nj, acc.w);
        }
    }
    for (; e < eend; e++) {
        uint2 ed = __ldg(&g_edge8[e]);
        float nj = __uint_as_float(ed.y);
        float4 v0 = H4[(size_t)ed.x * 16 + l16];
        acc.x = fmaf(v0.x, nj, acc.x);
        acc.y = fmaf(v0.y, nj, acc.y);
        acc.z = fmaf(v0.z, nj, acc.z);
        acc.w = fmaf(v0.w, nj, acc.w);
    }

    reinterpret_cast<float4*>(outp)[(size_t)node * 16 + l16] = acc;
}

// ---------------------------------------------------------------------------
// Launch: R10 two-stream row-half schedule.
// ---------------------------------------------------------------------------
extern "C" void kernel_launch(void* const* d_in, const int* in_sizes, int n_in,
                              void* d_out, int out_size) {
    const float* x  = (const float*)d_in[0];
    const void*  ei = d_in[1];
    const float* W1 = (const float*)d_in[2];
    const float* b1 = (const float*)d_in[3];
    const float* W2 = (const float*)d_in[4];
    const float* b2 = (const float*)d_in[5];
    const float* W3 = (const float*)d_in[6];
    const float* b3 = (const float*)d_in[7];
    float* out = (float*)d_out;

    const int N = in_sizes[0] / 128;
    const int E = in_sizes[1] / 2;
    const int T = 256;
    const int nb = (N + SCAN_CHUNK - 1) / SCAN_CHUNK;
    const int Nh = (N + 1) / 2;

    static cudaStream_t s2 = nullptr;
    static cudaEvent_t ev[8];
    if (!s2) {
        cudaStreamCreateWithFlags(&s2, cudaStreamNonBlocking);
        for (int i = 0; i < 8; i++)
            cudaEventCreateWithFlags(&ev[i], cudaEventDisableTiming);
    }

    const int gemmB_h0 = (Nh + 127) / 128;
    const int gemmB_h1 = (N - Nh + 127) / 128;
    const int aggB_h0 = (Nh * 32 + T - 1) / T;
    const int aggB_h1 = ((N - Nh) * 32 + T - 1) / T;
    const int agg64B_h0 = (((Nh + 1) / 2) * 32 + T - 1) / T;
    const int agg64B_h1 = (((N - Nh + 1) / 2) * 32 + T - 1) / T;

    // ---- fork: prep on s2 ----
    cudaEventRecord(ev[0], 0);
    cudaStreamWaitEvent(s2, ev[0], 0);

    detect_dtype_kernel<<<1, 32, 0, s2>>>(ei, E, N);
    count_kernel<<<(E + T - 1) / T, T, 0, s2>>>(ei, E);
    scan1_kernel<<<nb, 256, 0, s2>>>(N);
    scan2_kernel<<<1, 64, 0, s2>>>(nb, N);
    scan3_kernel<<<(N + T - 1) / T, T, 0, s2>>>(N);
    fill_kernel<<<(E + T - 1) / T, T, 0, s2>>>(ei, E);
    cudaEventRecord(ev[1], s2);           // prep done

    // ---- gemm1 (full) on s0, overlapping prep ----
    gemm_kernel<128, false, false><<<(N + 127) / 128, 256>>>(x, W1, 0, N);
    cudaEventRecord(ev[2], 0);            // H1 done

    // ---- layer-1 agg / layer-2 gemm halves ----
    cudaStreamWaitEvent(0, ev[1], 0);     // s0 needs CSR
    aggregate128_kernel<<<aggB_h0, T>>>(b1, 0, Nh);
    gemm_kernel<128, true, true><<<gemmB_h0, 256>>>(nullptr, W2, 0, Nh);
    cudaEventRecord(ev[3], 0);            // gemm2 h0 done

    cudaStreamWaitEvent(s2, ev[2], 0);    // s2 needs H1
    aggregate128_kernel<<<aggB_h1, T, 0, s2>>>(b1, Nh, N);
    gemm_kernel<128, true, true><<<gemmB_h1, 256, 0, s2>>>(nullptr, W2, Nh, N);
    cudaEventRecord(ev[4], s2);           // gemm2 h1 done

    // ---- layer-2 agg / layer-3 gemm halves ----
    cudaStreamWaitEvent(0, ev[4], 0);     // agg2 needs full H2
    aggregate128_kernel<<<aggB_h0, T>>>(b2, 0, Nh);
    gemm_kernel<64, true, true><<<gemmB_h0, 256>>>(nullptr, W3, 0, Nh);
    cudaEventRecord(ev[5], 0);            // gemm3 h0 done

    cudaStreamWaitEvent(s2, ev[3], 0);
    aggregate128_kernel<<<aggB_h1, T, 0, s2>>>(b2, Nh, N);
    gemm_kernel<64, true, true><<<gemmB_h1, 256, 0, s2>>>(nullptr, W3, Nh, N);
    cudaEventRecord(ev[6], s2);           // gemm3 h1 done

    // ---- layer-3 agg halves -> d_out ----
    cudaStreamWaitEvent(0, ev[6], 0);
    aggregate64_kernel<<<agg64B_h0, T>>>(b3, out, 0, Nh);

    cudaStreamWaitEvent(s2, ev[5], 0);
    aggregate64_kernel<<<agg64B_h1, T, 0, s2>>>(b3, out, Nh, N);
    cudaEventRecord(ev[7], s2);

    cudaStreamWaitEvent(0, ev[7], 0);
}

// round 14
// speedup vs baseline: 1.4365x; 1.1415x over previous
#include <cuda_runtime.h>
#include <cuda_fp16.h>
#include <cstdint>

// ---------------------------------------------------------------------------
// 3-layer GCN, symmetric norm D^{-1/2}(A+I)D^{-1/2}, self-loops.
// N=50000, E=640000, features 128 -> 128 -> 128 -> 64.
// R14: R10 schedule + H stored in fp16 (halves aggregate gather traffic and
// GEMM H-write traffic; deterministic rel_err ~5e-4, threshold 1e-3).
// ---------------------------------------------------------------------------

#define MAX_N 50048
#define MAX_E 640000
#define SCAN_CHUNK 1024

__device__ __align__(16) __half g_Hh[MAX_N * 128];  // H = X @ W  (fp16)
__device__ __align__(16) float  g_B[MAX_N * 128];   // layer output (fp32)
__device__ __align__(16) float  g_enorm[MAX_E];
__device__ __align__(16) int    g_src[MAX_E];
__device__ int   g_rowptr[MAX_N + 1];
__device__ int   g_cnt[MAX_N];                      // ZERO between replays
__device__ int   g_bsum[(MAX_N + SCAN_CHUNK - 1) / SCAN_CHUNK];
__device__ float g_dinv[MAX_N];
__device__ int   g_is64;

// ---------------------------------------------------------------------------
// f32x2 helpers
// ---------------------------------------------------------------------------
__device__ __forceinline__ unsigned long long dup_f32(float w) {
    unsigned long long r;
    asm("mov.b64 %0, {%1, %1};" : "=l"(r) : "f"(w));
    return r;
}
__device__ __forceinline__ void ffma2(unsigned long long& d,
                                      unsigned long long a,
                                      unsigned long long b) {
    asm("fma.rn.f32x2 %0, %1, %2, %0;" : "+l"(d) : "l"(a), "l"(b));
}
__device__ __forceinline__ void unpack2(unsigned long long v, float& lo, float& hi) {
    asm("mov.b64 {%0, %1}, %2;" : "=f"(lo), "=f"(hi) : "l"(v));
}
__device__ __forceinline__ uint32_t pack_h2(float a, float b) {
    __half2 h = __floats2half2_rn(a, b);
    return *reinterpret_cast<uint32_t*>(&h);
}

// ---------------------------------------------------------------------------
// Prep
// ---------------------------------------------------------------------------
__global__ void detect_dtype_kernel(const void* __restrict__ ei, int E, int N) {
    int tid = threadIdx.x;
    const long long* p = (const long long*)ei;
    int take = E < 128 ? E : 128;
    int bad = 0;
    for (int j = tid * 4; j < tid * 4 + 4; j++) {
        if (j < take) {
            long long v = p[j];
            if (v < 0 || v >= (long long)N) bad = 1;
        }
    }
    unsigned m = __ballot_sync(0xffffffffu, bad);
    if (tid == 0) g_is64 = (m == 0u);
}

__device__ __forceinline__ void decode_edge(const void* ei, int E, int e,
                                            int& s, int& d) {
    if (g_is64) {
        const long long* p = (const long long*)ei;
        s = (int)p[e];
        d = (int)p[E + e];
    } else {
        const int* p = (const int*)ei;
        s = p[e];
        d = p[E + e];
    }
}

__global__ void count_kernel(const void* __restrict__ ei, int E) {
    int e = blockIdx.x * blockDim.x + threadIdx.x;
    if (e >= E) return;
    int d;
    if (g_is64) d = (int)((const long long*)ei)[E + e];
    else        d = ((const int*)ei)[E + e];
    atomicAdd(&g_cnt[d], 1);
}

__global__ void scan1_kernel(int n) {
    __shared__ int warpsum[8];
    const int tid = threadIdx.x, lane = tid & 31, wid = tid >> 5;
    const int base = blockIdx.x * SCAN_CHUNK + tid * 4;

    int v[4] = {0, 0, 0, 0};
    if (base + 3 < n) {
        *reinterpret_cast<int4*>(v) = *reinterpret_cast<const int4*>(&g_cnt[base]);
    } else {
        for (int j = 0; j < 4; j++) if (base + j < n) v[j] = g_cnt[base + j];
    }
    #pragma unroll
    for (int j = 0; j < 4; j++)
        if (base + j < n) g_dinv[base + j] = rsqrtf((float)v[j] + 1.0f);

    int t0 = v[0], t1 = t0 + v[1], t2 = t1 + v[2], t3 = t2 + v[3];
    int x = t3;
    #pragma unroll
    for (int off = 1; off < 32; off <<= 1) {
        int t = __shfl_up_sync(0xffffffffu, x, off);
        if (lane >= off) x += t;
    }
    if (lane == 31) warpsum[wid] = x;
    __syncthreads();
    if (wid == 0 && lane < 8) {
        int w = warpsum[lane];
        #pragma unroll
        for (int off = 1; off < 8; off <<= 1) {
            int t = __shfl_up_sync(0xffu, w, off);
            if (lane >= off) w += t;
        }
        warpsum[lane] = w;
    }
    __syncthreads();

    int off = (x - t3) + (wid > 0 ? warpsum[wid - 1] : 0);
    int pre[4] = {0, t0, t1, t2};
    #pragma unroll
    for (int j = 0; j < 4; j++)
        if (base + j < n) g_rowptr[base + j] = off + pre[j];

    if (tid == 255) g_bsum[blockIdx.x] = warpsum[7];
}

__global__ void scan2_kernel(int nb, int n) {
    __shared__ int ws[2];
    int tid = threadIdx.x, lane = tid & 31, wid = tid >> 5;
    int v = (tid < nb) ? g_bsum[tid] : 0;
    int x = v;
    #pragma unroll
    for (int off = 1; off < 32; off <<= 1) {
        int t = __shfl_up_sync(0xffffffffu, x, off);
        if (lane >= off) x += t;
    }
    if (lane == 31) ws[wid] = x;
    __syncthreads();
    if (wid == 1) x += ws[0];
    if (tid < nb) g_bsum[tid] = x - v;
    if (tid == nb - 1) g_rowptr[n] = x;
}

__global__ void scan3_kernel(int n) {
    int i = blockIdx.x * blockDim.x + threadIdx.x;
    if (i < n) g_rowptr[i] += g_bsum[i >> 10];
}

__global__ void fill_kernel(const void* __restrict__ ei, int E) {
    int e = blockIdx.x * blockDim.x + threadIdx.x;
    if (e >= E) return;
    int s, d;
    decode_edge(ei, E, e, s, d);
    int pos = g_rowptr[d] + atomicSub(&g_cnt[d], 1) - 1;
    g_src[pos] = s;
    g_enorm[pos] = g_dinv[s] * g_dinv[d];
}

// ---------------------------------------------------------------------------
// FFMA2 register-tiled SGEMM over rows [rowBegin, rowEnd): g_Hh = X @ W (fp16)
// ---------------------------------------------------------------------------
template <int BN, bool RELU, bool FROM_GB>
__global__ __launch_bounds__(256, 2)
void gemm_kernel(const float* __restrict__ Xin,
                 const float* __restrict__ W, int rowBegin, int rowEnd) {
    constexpr int BM = 128, BK = 16;
    constexpr int TN = BN / 16;
    constexpr int WI = (BK * BN) / 1024;

    __shared__ float Xs[BK][BM + 4];
    __shared__ float Ws[BK][BN];

    const float* __restrict__ X = FROM_GB ? (const float*)g_B : Xin;

    const int tid = threadIdx.x;
    const int tx = tid & 15;
    const int ty = tid >> 4;
    const int rowBase = rowBegin + blockIdx.x * BM;

    const int xrow0 = tid >> 2, xkq0 = tid & 3;
    const int xrow1 = (tid + 256) >> 2, xkq1 = (tid + 256) & 3;
    const int r0 = rowBase + xrow0, r1 = rowBase + xrow1;

    float4 xr[2], wr[2];

    auto load_tile = [&](int kc) {
        xr[0] = make_float4(0.f, 0.f, 0.f, 0.f);
        xr[1] = make_float4(0.f, 0.f, 0.f, 0.f);
        if (r0 < rowEnd)
            xr[0] = *reinterpret_cast<const float4*>(&X[(size_t)r0 * 128 + kc + xkq0 * 4]);
        if (r1 < rowEnd)
            xr[1] = *reinterpret_cast<const float4*>(&X[(size_t)r1 * 128 + kc + xkq1 * 4]);
        if (RELU) {
            xr[0].x = fmaxf(xr[0].x, 0.f); xr[0].y = fmaxf(xr[0].y, 0.f);
            xr[0].z = fmaxf(xr[0].z, 0.f); xr[0].w = fmaxf(xr[0].w, 0.f);
            xr[1].x = fmaxf(xr[1].x, 0.f); xr[1].y = fmaxf(xr[1].y, 0.f);
            xr[1].z = fmaxf(xr[1].z, 0.f); xr[1].w = fmaxf(xr[1].w, 0.f);
        }
        #pragma unroll
        for (int i = 0; i < WI; i++) {
            int j = tid + 256 * i;
            int kk = j / (BN / 4);
            int cc = j % (BN / 4);
            wr[i] = *reinterpret_cast<const float4*>(&W[(size_t)(kc + kk) * BN + cc * 4]);
        }
    };
    auto store_tile = [&]() {
        Xs[xkq0 * 4 + 0][xrow0] = xr[0].x;
        Xs[xkq0 * 4 + 1][xrow0] = xr[0].y;
        Xs[xkq0 * 4 + 2][xrow0] = xr[0].z;
        Xs[xkq0 * 4 + 3][xrow0] = xr[0].w;
        Xs[xkq1 * 4 + 0][xrow1] = xr[1].x;
        Xs[xkq1 * 4 + 1][xrow1] = xr[1].y;
        Xs[xkq1 * 4 + 2][xrow1] = xr[1].z;
        Xs[xkq1 * 4 + 3][xrow1] = xr[1].w;
        #pragma unroll
        for (int i = 0; i < WI; i++) {
            int j = tid + 256 * i;
            int kk = j / (BN / 4);
            int cc = j % (BN / 4);
            *reinterpret_cast<float4*>(&Ws[kk][cc * 4]) = wr[i];
        }
    };

    unsigned long long acc2[4][TN];
    #pragma unroll
    for (int i = 0; i < 4; i++)
        #pragma unroll
        for (int j = 0; j < TN; j++) acc2[i][j] = 0ull;

    load_tile(0);
    store_tile();
    __syncthreads();

    for (int t = 0; t < 128 / BK; t++) {
        if (t + 1 < 128 / BK) load_tile((t + 1) * BK);

        #pragma unroll
        for (int k = 0; k < BK; k++) {
            const ulonglong2* ap =
                reinterpret_cast<const ulonglong2*>(&Xs[k][ty * 8]);
            ulonglong2 a01 = ap[0];
            ulonglong2 a23 = ap[1];
            unsigned long long a2[4] = {a01.x, a01.y, a23.x, a23.y};

            float bw[TN];
            #pragma unroll
            for (int j = 0; j < TN; j += 4)
                *reinterpret_cast<float4*>(&bw[j]) =
                    *reinterpret_cast<const float4*>(&Ws[k][tx * TN + j]);
            unsigned long long b2[TN];
            #pragma unroll
            for (int j = 0; j < TN; j++) b2[j] = dup_f32(bw[j]);

            #pragma unroll
            for (int rp = 0; rp < 4; rp++)
                #pragma unroll
                for (int j = 0; j < TN; j++)
                    ffma2(acc2[rp][j], a2[rp], b2[j]);
        }
        __syncthreads();
        if (t + 1 < 128 / BK) {
            store_tile();
            __syncthreads();
        }
    }

    // ---- epilogue: convert to fp16, vector store ----
    #pragma unroll
    for (int rp = 0; rp < 4; rp++) {
        float h0[TN], h1[TN];
        #pragma unroll
        for (int j = 0; j < TN; j++) unpack2(acc2[rp][j], h0[j], h1[j]);
        int row0 = rowBase + ty * 8 + 2 * rp;
        #pragma unroll
        for (int half = 0; half < 2; half++) {
            int row = row0 + half;
            if (row >= rowEnd) continue;
            float* h = half ? h1 : h0;
            uint32_t p[TN / 2];
            #pragma unroll
            for (int j = 0; j < TN / 2; j++)
                p[j] = pack_h2(h[2 * j], h[2 * j + 1]);
            __half* dst = &g_Hh[(size_t)row * BN + tx * TN];
            if (TN == 8)
                *reinterpret_cast<uint4*>(dst) =
                    make_uint4(p[0], p[1], p[2], p[3]);
            else
                *reinterpret_cast<uint2*>(dst) = make_uint2(p[0], p[1]);
        }
    }
}

// ---------------------------------------------------------------------------
// F=128 aggregation over [begin, end): warp per node, fp16 gathers.
// Each lane covers 4 features = 8B (uint2). Warp row read = 256B.
// ---------------------------------------------------------------------------
__device__ __forceinline__ float4 h4_to_f4(uint2 raw) {
    float2 f0 = __half22float2(*reinterpret_cast<__half2*>(&raw.x));
    float2 f1 = __half22float2(*reinterpret_cast<__half2*>(&raw.y));
    return make_float4(f0.x, f0.y, f1.x, f1.y);
}

__global__ void aggregate128_kernel(const float* __restrict__ bias,
                                    int begin, int end) {
    int node = begin + ((blockIdx.x * blockDim.x + threadIdx.x) >> 5);
    int lane = threadIdx.x & 31;
    if (node >= end) return;

    int e = g_rowptr[node];
    const int eend = g_rowptr[node + 1];

    const uint2* __restrict__ H2 = reinterpret_cast<const uint2*>(g_Hh);
    // row stride in uint2 units: 128 halves = 32 uint2
    float di = g_dinv[node];
    float s = di * di;
    float4 hd = h4_to_f4(__ldg(&H2[(size_t)node * 32 + lane]));
    float4 bb = reinterpret_cast<const float4*>(bias)[lane];
    float4 acc = make_float4(fmaf(hd.x, s, bb.x), fmaf(hd.y, s, bb.y),
                             fmaf(hd.z, s, bb.z), fmaf(hd.w, s, bb.w));

    for (; e + 7 < eend; e += 8) {
        int   si[8];
        float ni[8];
        #pragma unroll
        for (int j = 0; j < 8; j++) { si[j] = __ldg(&g_src[e + j]); ni[j] = __ldg(&g_enorm[e + j]); }
        uint2 raw[8];
        #pragma unroll
        for (int j = 0; j < 8; j++) raw[j] = __ldg(&H2[(size_t)si[j] * 32 + lane]);
        #pragma unroll
        for (int j = 0; j < 8; j++) {
            float4 v = h4_to_f4(raw[j]);
            acc.x = fmaf(v.x, ni[j], acc.x);
            acc.y = fmaf(v.y, ni[j], acc.y);
            acc.z = fmaf(v.z, ni[j], acc.z);
            acc.w = fmaf(v.w, ni[j], acc.w);
        }
    }
    for (; e < eend; e++) {
        int s0 = __ldg(&g_src[e]);
        float n0 = __ldg(&g_enorm[e]);
        float4 v = h4_to_f4(__ldg(&H2[(size_t)s0 * 32 + lane]));
        acc.x = fmaf(v.x, n0, acc.x);
        acc.y = fmaf(v.y, n0, acc.y);
        acc.z = fmaf(v.z, n0, acc.z);
        acc.w = fmaf(v.w, n0, acc.w);
    }

    reinterpret_cast<float4*>(g_B)[(size_t)node * 32 + lane] = acc;
}

// ---------------------------------------------------------------------------
// F=64 aggregation over [begin, end): two nodes per warp, fp16 gathers,
// writes d_out (fp32).
// ---------------------------------------------------------------------------
__global__ void aggregate64_kernel(const float* __restrict__ bias,
                                   float* __restrict__ outp,
                                   int begin, int end) {
    int warp = (blockIdx.x * blockDim.x + threadIdx.x) >> 5;
    int lane = threadIdx.x & 31;
    int node = begin + warp * 2 + (lane >> 4);
    int l16 = lane & 15;
    if (node >= end) return;

    int e = g_rowptr[node];
    const int eend = g_rowptr[node + 1];

    const uint2* __restrict__ H2 = reinterpret_cast<const uint2*>(g_Hh);
    // row stride in uint2 units: 64 halves = 16 uint2
    float di = g_dinv[node];
    float s = di * di;
    float4 hd = h4_to_f4(__ldg(&H2[(size_t)node * 16 + l16]));
    float4 bb = reinterpret_cast<const float4*>(bias)[l16];
    float4 acc = make_float4(fmaf(hd.x, s, bb.x), fmaf(hd.y, s, bb.y),
                             fmaf(hd.z, s, bb.z), fmaf(hd.w, s, bb.w));

    for (; e + 3 < eend; e += 4) {
        int s0 = __ldg(&g_src[e]), s1 = __ldg(&g_src[e + 1]);
        int s2 = __ldg(&g_src[e + 2]), s3 = __ldg(&g_src[e + 3]);
        float n0 = __ldg(&g_enorm[e]), n1 = __ldg(&g_enorm[e + 1]);
        float n2 = __ldg(&g_enorm[e + 2]), n3 = __ldg(&g_enorm[e + 3]);
        float4 v0 = h4_to_f4(__ldg(&H2[(size_t)s0 * 16 + l16]));
        float4 v1 = h4_to_f4(__ldg(&H2[(size_t)s1 * 16 + l16]));
        float4 v2 = h4_to_f4(__ldg(&H2[(size_t)s2 * 16 + l16]));
        float4 v3 = h4_to_f4(__ldg(&H2[(size_t)s3 * 16 + l16]));
        acc.x += v0.x * n0 + v1.x * n1 + v2.x * n2 + v3.x * n3;
        acc.y += v0.y * n0 + v1.y * n1 + v2.y * n2 + v3.y * n3;
        acc.z += v0.z * n0 + v1.z * n1 + v2.z * n2 + v3.z * n3;
        acc.w += v0.w * n0 + v1.w * n1 + v2.w * n2 + v3.w * n3;
    }
    for (; e < eend; e++) {
        int s0 = __ldg(&g_src[e]);
        float n0 = __ldg(&g_enorm[e]);
        float4 v = h4_to_f4(__ldg(&H2[(size_t)s0 * 16 + l16]));
        acc.x = fmaf(v.x, n0, acc.x);
        acc.y = fmaf(v.y, n0, acc.y);
        acc.z = fmaf(v.z, n0, acc.z);
        acc.w = fmaf(v.w, n0, acc.w);
    }

    reinterpret_cast<float4*>(outp)[(size_t)node * 16 + l16] = acc;
}

// ---------------------------------------------------------------------------
// Launch: R10 two-stream row-half schedule.
// ---------------------------------------------------------------------------
extern "C" void kernel_launch(void* const* d_in, const int* in_sizes, int n_in,
                              void* d_out, int out_size) {
    const float* x  = (const float*)d_in[0];
    const void*  ei = d_in[1];
    const float* W1 = (const float*)d_in[2];
    const float* b1 = (const float*)d_in[3];
    const float* W2 = (const float*)d_in[4];
    const float* b2 = (const float*)d_in[5];
    const float* W3 = (const float*)d_in[6];
    const float* b3 = (const float*)d_in[7];
    float* out = (float*)d_out;

    const int N = in_sizes[0] / 128;
    const int E = in_sizes[1] / 2;
    const int T = 256;
    const int nb = (N + SCAN_CHUNK - 1) / SCAN_CHUNK;
    const int Nh = (N + 1) / 2;

    static cudaStream_t s2 = nullptr;
    static cudaEvent_t ev[8];
    if (!s2) {
        cudaStreamCreateWithFlags(&s2, cudaStreamNonBlocking);
        for (int i = 0; i < 8; i++)
            cudaEventCreateWithFlags(&ev[i], cudaEventDisableTiming);
    }

    const int gemmB_h0 = (Nh + 127) / 128;
    const int gemmB_h1 = (N - Nh + 127) / 128;
    const int aggB_h0 = (Nh * 32 + T - 1) / T;
    const int aggB_h1 = ((N - Nh) * 32 + T - 1) / T;
    const int agg64B_h0 = (((Nh + 1) / 2) * 32 + T - 1) / T;
    const int agg64B_h1 = (((N - Nh + 1) / 2) * 32 + T - 1) / T;

    // ---- fork: prep on s2 ----
    cudaEventRecord(ev[0], 0);
    cudaStreamWaitEvent(s2, ev[0], 0);

    detect_dtype_kernel<<<1, 32, 0, s2>>>(ei, E, N);
    count_kernel<<<(E + T - 1) / T, T, 0, s2>>>(ei, E);
    scan1_kernel<<<nb, 256, 0, s2>>>(N);
    scan2_kernel<<<1, 64, 0, s2>>>(nb, N);
    scan3_kernel<<<(N + T - 1) / T, T, 0, s2>>>(N);
    fill_kernel<<<(E + T - 1) / T, T, 0, s2>>>(ei, E);
    cudaEventRecord(ev[1], s2);           // prep done

    // ---- gemm1 (full) on s0, overlapping prep ----
    gemm_kernel<128, false, false><<<(N + 127) / 128, 256>>>(x, W1, 0, N);
    cudaEventRecord(ev[2], 0);            // H1 done

    // ---- layer-1 agg / layer-2 gemm halves ----
    cudaStreamWaitEvent(0, ev[1], 0);     // s0 needs CSR
    aggregate128_kernel<<<aggB_h0, T>>>(b1, 0, Nh);
    gemm_kernel<128, true, true><<<gemmB_h0, 256>>>(nullptr, W2, 0, Nh);
    cudaEventRecord(ev[3], 0);            // gemm2 h0 done

    cudaStreamWaitEvent(s2, ev[2], 0);    // s2 needs H1
    aggregate128_kernel<<<aggB_h1, T, 0, s2>>>(b1, Nh, N);
    gemm_kernel<128, true, true><<<gemmB_h1, 256, 0, s2>>>(nullptr, W2, Nh, N);
    cudaEventRecord(ev[4], s2);           // gemm2 h1 done

    // ---- layer-2 agg / layer-3 gemm halves ----
    cudaStreamWaitEvent(0, ev[4], 0);     // agg2 needs full H2
    aggregate128_kernel<<<aggB_h0, T>>>(b2, 0, Nh);
    gemm_kernel<64, true, true><<<gemmB_h0, 256>>>(nullptr, W3, 0, Nh);
    cudaEventRecord(ev[5], 0);            // gemm3 h0 done

    cudaStreamWaitEvent(s2, ev[3], 0);
    aggregate128_kernel<<<aggB_h1, T, 0, s2>>>(b2, Nh, N);
    gemm_kernel<64, true, true><<<gemmB_h1, 256, 0, s2>>>(nullptr, W3, Nh, N);
    cudaEventRecord(ev[6], s2);           // gemm3 h1 done

    // ---- layer-3 agg halves -> d_out ----
    cudaStreamWaitEvent(0, ev[6], 0);
    aggregate64_kernel<<<agg64B_h0, T>>>(b3, out, 0, Nh);

    cudaStreamWaitEvent(s2, ev[5], 0);
    aggregate64_kernel<<<agg64B_h1, T, 0, s2>>>(b3, out, Nh, N);
    cudaEventRecord(ev[7], s2);

    cudaStreamWaitEvent(0, ev[7], 0);
}